// round 14
// baseline (speedup 1.0000x reference)
#include <cuda_runtime.h>

// SNN XOR net — I-cache round.
// All R13 wins kept: FSET spike, beta/reset as FFMA-imm (bit-exact),
// st.global.cs.v4 [base + IMM] streaming stores, 128thr x 2048 + 30KB ballast.
// New: t-loop re-rolled to 10 iterations x 2 unrolled steps (forced unroll 1).
// Hot body shrinks ~29KB -> ~3KB: fits the 6KB L0 I$ (was streaming through
// L1.5), removing the per-instr I$ tax. Store imm offsets are {0, BQ*16}=4MB,
// inside the 24-bit STG offset field; base bumps 2*BQ*16 per iteration.

#define THR 1.0f

__device__ __forceinline__ float fset_gt(float a, float b) {
    float d;
    asm("set.gt.f32.f32 %0, %1, %2;" : "=f"(d) : "f"(a), "f"(b));
    return d;  // 1.0f if a > b else 0.0f
}

template <int BQ>   // BQ = B/4 groups (compile-time); BQ==0 -> runtime path
__global__ void __launch_bounds__(128, 7) snn_xornet_kernel(
    const float* __restrict__ x,    // [B,2]
    const float* __restrict__ w1,   // [4,2]
    const float* __restrict__ w2,   // [1,4]
    float* __restrict__ out,        // [T,B]
    int B)
{
    const int i = blockIdx.x * blockDim.x + threadIdx.x;  // group of 4 elems
    if (i * 4 >= B) return;

    float w1r[4][2];
#pragma unroll
    for (int h = 0; h < 4; h++) {
        w1r[h][0] = __ldg(&w1[2 * h + 0]);
        w1r[h][1] = __ldg(&w1[2 * h + 1]);
    }
    float w2r[4];
#pragma unroll
    for (int h = 0; h < 4; h++) w2r[h] = __ldg(&w2[h]);

    const float4 xa = reinterpret_cast<const float4*>(x)[2 * i + 0];
    const float4 xb = reinterpret_cast<const float4*>(x)[2 * i + 1];
    const float xs[4][2] = {{xa.x, xa.y}, {xa.z, xa.w}, {xb.x, xb.y}, {xb.z, xb.w}};

    // cur = x @ w1^T (identical rounding to all passing kernels)
    float cur[4][4];
#pragma unroll
    for (int j = 0; j < 4; j++)
#pragma unroll
        for (int h = 0; h < 4; h++)
            cur[j][h] = fmaf(xs[j][0], w1r[h][0], xs[j][1] * w1r[h][1]);

    float m1[4][4], s1[4][4];
    float m2[4], s2[4];
#pragma unroll
    for (int j = 0; j < 4; j++) {
        m2[j] = 0.0f; s2[j] = 0.0f;
#pragma unroll
        for (int h = 0; h < 4; h++) { m1[j][h] = 0.0f; s1[j][h] = 0.0f; }
    }

    float4* base = reinterpret_cast<float4*>(out) + i;   // single base register

    // One bit-exact timestep; store via immediate offset off the rolling base.
#define SNN_STEP(T_)                                                          \
    {                                                                         \
        float4 v;                                                             \
        _Pragma("unroll")                                                     \
        for (int j = 0; j < 4; j++) {                                         \
            float acc = 0.0f;                                                 \
            _Pragma("unroll")                                                 \
            for (int h = 0; h < 4; h++) {                                     \
                float m = fmaf(m1[j][h], 0.9f, cur[j][h]);                    \
                m = fmaf(s1[j][h], -1.0f, m);                                 \
                m1[j][h] = m;                                                 \
                const float sp = fset_gt(m, THR);                             \
                s1[j][h] = sp;                                                \
                acc = fmaf(sp, w2r[h], acc);                                  \
            }                                                                 \
            float mo = fmaf(m2[j], 0.9f, acc);                                \
            mo = fmaf(s2[j], -1.0f, mo);                                      \
            m2[j] = mo;                                                       \
            const float so = fset_gt(mo, THR);                                \
            s2[j] = so;                                                       \
            if (j == 0) v.x = so;                                             \
            else if (j == 1) v.y = so;                                        \
            else if (j == 2) v.z = so;                                        \
            else v.w = so;                                                    \
        }                                                                     \
        if (BQ > 0) {                                                         \
            asm volatile(                                                     \
                "st.global.cs.v4.f32 [%0+%5], {%1, %2, %3, %4};"             \
                :: "l"(base), "f"(v.x), "f"(v.y), "f"(v.z), "f"(v.w),         \
                   "n"((long)(T_) * (long)BQ * 16L)                           \
                : "memory");                                                  \
        } else {                                                              \
            __stcs(base + (size_t)(T_) * (size_t)(B >> 2), v);                \
        }                                                                     \
    }

    // 10 iterations x 2 steps: hot body ~3KB, L0-resident.
#pragma unroll 1
    for (int tt = 0; tt < 10; tt++) {
        SNN_STEP(0)
        SNN_STEP(1)
        base += 2 * (size_t)((BQ > 0) ? BQ : (B >> 2));
    }
#undef SNN_STEP
}

extern "C" void kernel_launch(void* const* d_in, const int* in_sizes, int n_in,
                              void* d_out, int out_size) {
    const float* x  = (const float*)d_in[0];   // [B,2]
    const float* w1 = (const float*)d_in[1];   // [4,2]
    const float* w2 = (const float*)d_in[2];   // [1,4]
    float* out = (float*)d_out;                // [T,B,1]

    const int B = in_sizes[0] / 2;
    const int threads = 128;
    const int blocks = (B / 4 + threads - 1) / threads;   // 2048
    const size_t ballast = 30 * 1024;          // 7 blocks/SM -> 98.8% fill
    if (B == 1048576) {
        snn_xornet_kernel<262144><<<blocks, threads, ballast>>>(x, w1, w2, out, B);
    } else {
        snn_xornet_kernel<0><<<blocks, threads, ballast>>>(x, w1, w2, out, B);
    }
}

// round 15
// speedup vs baseline: 1.0243x; 1.0243x over previous
#include <cuda_runtime.h>

// SNN XOR net — R13 configuration (best: 16.83us), resubmitted verbatim to
// confirm reproducibility. R14's loop re-roll regressed (I$ tax was already
// prefetch-overlapped; re-roll added alu-pipe loop overhead) — full unroll
// restored.
// Wins accumulated here:
//  - FSET spike as 1.0/0.0 (one alu op feeds reset, layer-2 acc, and output)
//  - beta & reset as FFMA src1-immediate (rt 1, bit-exact commute)
//  - st.global.cs.v4 [base + compile-time IMM] streaming stores: one base
//    register for all 20 stores, evict-first policy
//  - 128thr x 2048 blocks + 30KB smem ballast -> 7 blocks/SM, 1.98 waves,
//    98.8% average fill

#define T_STEPS 20
#define THR 1.0f

__device__ __forceinline__ float fset_gt(float a, float b) {
    float d;
    asm("set.gt.f32.f32 %0, %1, %2;" : "=f"(d) : "f"(a), "f"(b));
    return d;  // 1.0f if a > b else 0.0f
}

template <int BQ>   // BQ = B/4 groups (compile-time); BQ==0 -> runtime path
__global__ void __launch_bounds__(128, 7) snn_xornet_kernel(
    const float* __restrict__ x,    // [B,2]
    const float* __restrict__ w1,   // [4,2]
    const float* __restrict__ w2,   // [1,4]
    float* __restrict__ out,        // [T,B]
    int B)
{
    const int i = blockIdx.x * blockDim.x + threadIdx.x;  // group of 4 elems
    if (i * 4 >= B) return;

    float w1r[4][2];
#pragma unroll
    for (int h = 0; h < 4; h++) {
        w1r[h][0] = __ldg(&w1[2 * h + 0]);
        w1r[h][1] = __ldg(&w1[2 * h + 1]);
    }
    float w2r[4];
#pragma unroll
    for (int h = 0; h < 4; h++) w2r[h] = __ldg(&w2[h]);

    const float4 xa = reinterpret_cast<const float4*>(x)[2 * i + 0];
    const float4 xb = reinterpret_cast<const float4*>(x)[2 * i + 1];
    const float xs[4][2] = {{xa.x, xa.y}, {xa.z, xa.w}, {xb.x, xb.y}, {xb.z, xb.w}};

    // cur = x @ w1^T (identical rounding to all passing kernels)
    float cur[4][4];
#pragma unroll
    for (int j = 0; j < 4; j++)
#pragma unroll
        for (int h = 0; h < 4; h++)
            cur[j][h] = fmaf(xs[j][0], w1r[h][0], xs[j][1] * w1r[h][1]);

    float m1[4][4], s1[4][4];
    float m2[4], s2[4];
#pragma unroll
    for (int j = 0; j < 4; j++) {
        m2[j] = 0.0f; s2[j] = 0.0f;
#pragma unroll
        for (int h = 0; h < 4; h++) { m1[j][h] = 0.0f; s1[j][h] = 0.0f; }
    }

    float4* base = reinterpret_cast<float4*>(out) + i;   // single base register

    // One timestep of the bit-exact recurrence; stores via immediate offset.
#define SNN_STEP(T_)                                                          \
    {                                                                         \
        float4 v;                                                             \
        _Pragma("unroll")                                                     \
        for (int j = 0; j < 4; j++) {                                         \
            float acc = 0.0f;                                                 \
            _Pragma("unroll")                                                 \
            for (int h = 0; h < 4; h++) {                                     \
                float m = fmaf(m1[j][h], 0.9f, cur[j][h]);                    \
                m = fmaf(s1[j][h], -1.0f, m);                                 \
                m1[j][h] = m;                                                 \
                const float sp = fset_gt(m, THR);                             \
                s1[j][h] = sp;                                                \
                acc = fmaf(sp, w2r[h], acc);                                  \
            }                                                                 \
            float mo = fmaf(m2[j], 0.9f, acc);                                \
            mo = fmaf(s2[j], -1.0f, mo);                                      \
            m2[j] = mo;                                                       \
            const float so = fset_gt(mo, THR);                                \
            s2[j] = so;                                                       \
            if (j == 0) v.x = so;                                             \
            else if (j == 1) v.y = so;                                        \
            else if (j == 2) v.z = so;                                        \
            else v.w = so;                                                    \
        }                                                                     \
        if (BQ > 0) {                                                         \
            asm volatile(                                                     \
                "st.global.cs.v4.f32 [%0+%5], {%1, %2, %3, %4};"             \
                :: "l"(base), "f"(v.x), "f"(v.y), "f"(v.z), "f"(v.w),         \
                   "n"((long)(T_) * (long)BQ * 16L)                           \
                : "memory");                                                  \
        } else {                                                              \
            __stcs(base + (size_t)(T_) * (size_t)(B >> 2), v);                \
        }                                                                     \
    }

    SNN_STEP(0)  SNN_STEP(1)  SNN_STEP(2)  SNN_STEP(3)  SNN_STEP(4)
    SNN_STEP(5)  SNN_STEP(6)  SNN_STEP(7)  SNN_STEP(8)  SNN_STEP(9)
    SNN_STEP(10) SNN_STEP(11) SNN_STEP(12) SNN_STEP(13) SNN_STEP(14)
    SNN_STEP(15) SNN_STEP(16) SNN_STEP(17) SNN_STEP(18) SNN_STEP(19)
#undef SNN_STEP
}

extern "C" void kernel_launch(void* const* d_in, const int* in_sizes, int n_in,
                              void* d_out, int out_size) {
    const float* x  = (const float*)d_in[0];   // [B,2]
    const float* w1 = (const float*)d_in[1];   // [4,2]
    const float* w2 = (const float*)d_in[2];   // [1,4]
    float* out = (float*)d_out;                // [T,B,1]

    const int B = in_sizes[0] / 2;
    const int threads = 128;
    const int blocks = (B / 4 + threads - 1) / threads;
    const size_t ballast = 30 * 1024;          // 7 blocks/SM -> 98.8% fill
    if (B == 1048576) {
        snn_xornet_kernel<262144><<<blocks, threads, ballast>>>(x, w1, w2, out, B);
    } else {
        snn_xornet_kernel<0><<<blocks, threads, ballast>>>(x, w1, w2, out, B);
    }
}